// round 1
// baseline (speedup 1.0000x reference)
#include <cuda_runtime.h>
#include <cuda_bf16.h>
#include <math.h>

#define HIDDEN   256
#define NQ       300
#define BS       2
#define LVLS     4
#define NHEADS   8
#define TOTALPIX 21760
#define BQ       (BS*NQ)          // 600
#define NROWS    (LVLS*BS*NQ)     // 2400
#define XCOLS    3136

// ---------------- scratch (static device globals; no runtime alloc) ----------
__device__ float g_gate[BQ * NHEADS * HIDDEN];   // 600 x 2048
__device__ float g_proj[BS * TOTALPIX * 64];     // projected memory
__device__ float g_X  [NROWS * XCOLS];           // MLP input rows
__device__ float g_H1 [NROWS * 256];
__device__ float g_H2 [NROWS * 512];
__device__ float g_H3 [NROWS * 512];
__device__ float g_pts[NROWS * 16];

__device__ __constant__ int c_dim[4]   = {128, 64, 32, 16};
__device__ __constant__ int c_start[4] = {0, 16384, 20480, 21504};

// ---------------- shared geometry helper (roi_align sampling) ----------------
// One 14x14 sub-sample (si,sj) of a box -> 4 bilinear corners.
// Weights include the 0.25 (2x2 mean) factor and the validity mask.
__device__ __forceinline__ void sample4(float sx, float sy, float bw, float bh,
                                        int W, int si, int sj,
                                        int idx[4], float wt[4]) {
    float Wf = (float)W;
    float ty = (float)(si >> 1) + 0.25f + 0.5f * (float)(si & 1);
    float tx = (float)(sj >> 1) + 0.25f + 0.5f * (float)(sj & 1);
    float y = sy + bh * ty;
    float x = sx + bw * tx;
    bool valid = (y >= -1.f) && (y <= Wf) && (x >= -1.f) && (x <= Wf);
    float yc = fminf(fmaxf(y, 0.f), Wf - 1.f);
    float xc = fminf(fmaxf(x, 0.f), Wf - 1.f);
    float y0 = fminf(floorf(yc), Wf - 2.f);
    float x0 = fminf(floorf(xc), Wf - 2.f);
    float ly = yc - y0, lx = xc - x0;
    int yi = (int)y0, xi = (int)x0;
    int p = yi * W + xi;
    float vm = valid ? 0.25f : 0.f;
    float oy = 1.f - ly, ox = 1.f - lx;
    idx[0] = p;       wt[0] = oy * ox * vm;
    idx[1] = p + 1;   wt[1] = oy * lx * vm;
    idx[2] = p + W;   wt[2] = ly * ox * vm;
    idx[3] = p + W + 1; wt[3] = ly * lx * vm;
}

__device__ __forceinline__ void box_geom(const float* __restrict__ r6, int W,
                                         float& sx, float& sy, float& bw, float& bh) {
    float Wf = (float)W;
    float cx = r6[0], cy = r6[1];
    float x1 = fminf(fmaxf(cx - r6[2], 0.f), 1.f) * Wf;
    float y1 = fminf(fmaxf(cy - r6[3], 0.f), 1.f) * Wf;
    float x2 = fminf(fmaxf(cx + r6[4], 0.f), 1.f) * Wf;
    float y2 = fminf(fmaxf(cy + r6[5], 0.f), 1.f) * Wf;
    sx = x1 - 0.5f; sy = y1 - 0.5f;
    bw = (x2 - x1) / 7.f; bh = (y2 - y1) / 7.f;
}

// ---------------- generic fp32 tiled GEMM: C = epi(A(MxK) @ B(KxN) + bias) ---
// BM=BN=64, BK=16, 256 threads, 4x4 microtile. K must be a multiple of 16
// and N a multiple of 4 (true for all call sites here).
template <int EPI>   // 0 none, 1 relu, 2 sigmoid, 3 tanh
__global__ __launch_bounds__(256)
void gemm_kernel(const float* __restrict__ A, const float* __restrict__ B,
                 const float* __restrict__ bias, float* __restrict__ C,
                 int M, int N, int K) {
    __shared__ float As[16][64];
    __shared__ float Bs[16][64];
    int bn0 = blockIdx.x * 64, bm0 = blockIdx.y * 64;
    int tid = threadIdx.x;
    int tc = (tid & 15) * 4;
    int tr = (tid >> 4) * 4;
    int la_m = tid >> 2;            // 0..63
    int la_k = (tid & 3) * 4;       // 0,4,8,12
    int lb_k = tid >> 4;            // 0..15
    int lb_n = (tid & 15) * 4;
    float acc[4][4] = {};

    for (int k0 = 0; k0 < K; k0 += 16) {
        float4 av = make_float4(0.f, 0.f, 0.f, 0.f);
        if (bm0 + la_m < M)
            av = *(const float4*)(A + (size_t)(bm0 + la_m) * K + k0 + la_k);
        As[la_k + 0][la_m] = av.x;
        As[la_k + 1][la_m] = av.y;
        As[la_k + 2][la_m] = av.z;
        As[la_k + 3][la_m] = av.w;
        float4 bv = make_float4(0.f, 0.f, 0.f, 0.f);
        if (bn0 + lb_n < N)
            bv = *(const float4*)(B + (size_t)(k0 + lb_k) * N + bn0 + lb_n);
        *(float4*)&Bs[lb_k][lb_n] = bv;
        __syncthreads();
#pragma unroll
        for (int k = 0; k < 16; k++) {
            float4 a4 = *(const float4*)&As[k][tr];
            float4 b4 = *(const float4*)&Bs[k][tc];
            float avv[4] = {a4.x, a4.y, a4.z, a4.w};
            float bvv[4] = {b4.x, b4.y, b4.z, b4.w};
#pragma unroll
            for (int i = 0; i < 4; i++)
#pragma unroll
                for (int j = 0; j < 4; j++)
                    acc[i][j] += avv[i] * bvv[j];
        }
        __syncthreads();
    }
#pragma unroll
    for (int i = 0; i < 4; i++) {
        int m = bm0 + tr + i;
        if (m >= M) continue;
#pragma unroll
        for (int j = 0; j < 4; j++) {
            int n = bn0 + tc + j;
            if (n >= N) continue;
            float v = acc[i][j] + (bias ? bias[n] : 0.f);
            if (EPI == 1) v = fmaxf(v, 0.f);
            else if (EPI == 2) v = 1.f / (1.f + expf(-v));
            else if (EPI == 3) v = tanhf(v);
            C[(size_t)m * N + n] = v;
        }
    }
}

// ---------------- build X rows: relu(roi_align(proj) + p1_b), flattened ------
// one block per (lvl, b, q); 256 threads
__global__ __launch_bounds__(256)
void build_x_kernel(const float* __restrict__ ref, const float* __restrict__ p1_b) {
    int blk = blockIdx.x;                 // lvl*600 + b*300 + q
    int lvl = blk / BQ;
    int rem = blk - lvl * BQ;
    int b = rem / NQ;
    int q = rem - b * NQ;
    int W = c_dim[lvl];
    int start = c_start[lvl];
    const float* r6 = ref + ((size_t)(b * NQ + q) * LVLS + lvl) * 6;
    float sx, sy, bw, bh;
    box_geom(r6, W, sx, sy, bw, bh);

    __shared__ int   sIdx[196][4];
    __shared__ float sW[196][4];
    int tid = threadIdx.x;
    if (tid < 196) {
        int si = tid / 14, sj = tid - si * 14;
        int idx4[4]; float wt4[4];
        sample4(sx, sy, bw, bh, W, si, sj, idx4, wt4);
#pragma unroll
        for (int k = 0; k < 4; k++) { sIdx[tid][k] = idx4[k]; sW[tid][k] = wt4[k]; }
    }
    __syncthreads();

    int d = tid & 63;
    int g = tid >> 6;                      // 0..3
    const float* projB = g_proj + ((size_t)b * TOTALPIX + start) * 64 + d;
    float bias = p1_b[d];
    float* Xrow = g_X + (size_t)blk * XCOLS + d * 49;
    for (int bin = g; bin < 49; bin += 4) {
        int h = bin / 7, w_ = bin - h * 7;
        float acc = 0.f;
#pragma unroll
        for (int s2 = 0; s2 < 4; s2++) {
            int s = (2 * h + (s2 >> 1)) * 14 + 2 * w_ + (s2 & 1);
#pragma unroll
            for (int cr = 0; cr < 4; cr++)
                acc += sW[s][cr] * projB[(size_t)sIdx[s][cr] * 64];
        }
        Xrow[bin] = fmaxf(acc + bias, 0.f);
    }
}

// ---------------- finalize: grid_sample recompute + gate + softmax combine ---
// one block per (b, q); 256 threads (= channel)
__global__ __launch_bounds__(256)
void finalize_kernel(const float* __restrict__ memory, const float* __restrict__ ref,
                     const float* __restrict__ a2w, const float* __restrict__ a2b,
                     float* __restrict__ out) {
    int bq = blockIdx.x;                   // b*300 + q
    int b = bq / NQ;
    int tid = threadIdx.x;

    __shared__ float qe_s[32][HIDDEN];     // 32 KB
    __shared__ float wArr[2048];           // 8 KB
    __shared__ unsigned short iArr[2048];  // 4 KB (pixel index < 43520)
    __shared__ float logits[32];
    __shared__ float wgt[32];

    // phase 0: precompute all (lvl,head,bin,sample,corner) gather entries
    for (int e = tid; e < 2048; e += 256) {
        int lvl = e >> 9;
        int head = (e >> 6) & 7;
        int bc = (e >> 4) & 3;             // which of 4 roi-bin corners
        int sm = (e >> 2) & 3;             // which 2x2 subsample of the bin
        int cr = e & 3;                    // which bilinear pixel corner
        int W = c_dim[lvl];
        int start = c_start[lvl];
        const float* r6 = ref + ((size_t)bq * LVLS + lvl) * 6;
        float sx, sy, bw, bh;
        box_geom(r6, W, sx, sy, bw, bh);

        int row = lvl * BQ + bq;
        float gx = g_pts[row * 16 + 2 * head];
        float gy = g_pts[row * 16 + 2 * head + 1];
        float ix = ((gx + 1.f) * 7.f - 1.f) * 0.5f;
        float iy = ((gy + 1.f) * 7.f - 1.f) * 0.5f;
        float bxf = floorf(ix), byf = floorf(iy);
        float lx = ix - bxf, ly = iy - byf;
        int dby = bc >> 1, dbx = bc & 1;
        int bi = (int)byf + dby, bj = (int)bxf + dbx;
        float wb = (dby ? ly : 1.f - ly) * (dbx ? lx : 1.f - lx);
        if (bi < 0 || bi > 6 || bj < 0 || bj > 6) wb = 0.f;
        int si = 2 * bi + (sm >> 1);
        int sj = 2 * bj + (sm & 1);
        int idx4[4]; float wt4[4];
        sample4(sx, sy, bw, bh, W, si, sj, idx4, wt4);
        wArr[e] = wb * wt4[cr];
        iArr[e] = (unsigned short)(b * TOTALPIX + start + idx4[cr]);
    }
    __syncthreads();

    // phase 1: gather sampled vectors, apply gate
    const float* gateRow = g_gate + (size_t)bq * (NHEADS * HIDDEN);
    int c = tid;
    for (int lh = 0; lh < 32; lh++) {
        float a0 = 0.f, a1 = 0.f, a2 = 0.f, a3 = 0.f;
        int eb = lh << 6;
#pragma unroll 4
        for (int e = 0; e < 64; e += 4) {
            float w0 = wArr[eb + e + 0];
            float w1 = wArr[eb + e + 1];
            float w2 = wArr[eb + e + 2];
            float w3 = wArr[eb + e + 3];
            if (w0 != 0.f) a0 += w0 * memory[(size_t)iArr[eb + e + 0] * HIDDEN + c];
            if (w1 != 0.f) a1 += w1 * memory[(size_t)iArr[eb + e + 1] * HIDDEN + c];
            if (w2 != 0.f) a2 += w2 * memory[(size_t)iArr[eb + e + 2] * HIDDEN + c];
            if (w3 != 0.f) a3 += w3 * memory[(size_t)iArr[eb + e + 3] * HIDDEN + c];
        }
        qe_s[lh][c] = ((a0 + a1) + (a2 + a3)) * gateRow[(lh & 7) * HIDDEN + c];
    }
    __syncthreads();

    // phase 2: logits = qe @ a2w + b
    int warp = tid >> 5, lane = tid & 31;
    for (int r = warp; r < 32; r += 8) {
        float s = 0.f;
#pragma unroll
        for (int c2 = lane; c2 < HIDDEN; c2 += 32) s += qe_s[r][c2] * a2w[c2];
#pragma unroll
        for (int o = 16; o; o >>= 1) s += __shfl_xor_sync(0xffffffffu, s, o);
        if (lane == 0) logits[r] = s + a2b[0];
    }
    __syncthreads();

    // phase 3: softmax over 32
    if (tid < 32) {
        float l = logits[tid];
        float mx = l;
#pragma unroll
        for (int o = 16; o; o >>= 1) mx = fmaxf(mx, __shfl_xor_sync(0xffffffffu, mx, o));
        float ex = expf(l - mx);
        float sum = ex;
#pragma unroll
        for (int o = 16; o; o >>= 1) sum += __shfl_xor_sync(0xffffffffu, sum, o);
        wgt[tid] = ex / sum;
    }
    __syncthreads();

    // phase 4: weighted sum
    float o = 0.f;
#pragma unroll
    for (int r = 0; r < 32; r++) o += wgt[r] * qe_s[r][c];
    out[(size_t)bq * HIDDEN + c] = o;
}

// -----------------------------------------------------------------------------
static inline int cdiv(int a, int b) { return (a + b - 1) / b; }

extern "C" void kernel_launch(void* const* d_in, const int* in_sizes, int n_in,
                              void* d_out, int out_size) {
    const float* tgt    = (const float*)d_in[0];
    const float* memory = (const float*)d_in[1];
    const float* ref    = (const float*)d_in[2];
    // d_in[3] level_start_index: known statically
    const float* p1_w = (const float*)d_in[4];
    const float* p1_b = (const float*)d_in[5];
    const float* w1   = (const float*)d_in[6];
    const float* b1   = (const float*)d_in[7];
    const float* w2   = (const float*)d_in[8];
    const float* b2   = (const float*)d_in[9];
    const float* w3   = (const float*)d_in[10];
    const float* b3   = (const float*)d_in[11];
    const float* w4   = (const float*)d_in[12];
    const float* b4   = (const float*)d_in[13];
    const float* a1w  = (const float*)d_in[14];
    const float* a1b  = (const float*)d_in[15];
    const float* a2w  = (const float*)d_in[16];
    const float* a2b  = (const float*)d_in[17];
    float* out = (float*)d_out;

    float *gate, *proj, *X, *H1, *H2, *H3, *pts;
    cudaGetSymbolAddress((void**)&gate, g_gate);
    cudaGetSymbolAddress((void**)&proj, g_proj);
    cudaGetSymbolAddress((void**)&X,    g_X);
    cudaGetSymbolAddress((void**)&H1,   g_H1);
    cudaGetSymbolAddress((void**)&H2,   g_H2);
    cudaGetSymbolAddress((void**)&H3,   g_H3);
    cudaGetSymbolAddress((void**)&pts,  g_pts);

    dim3 t(256);
    // gate = sigmoid(tgt @ attn1_w + attn1_b)   (600 x 2048, K=256)
    gemm_kernel<2><<<dim3(2048 / 64, cdiv(BQ, 64)), t>>>(tgt, a1w, a1b, gate, BQ, 2048, 256);
    // proj = memory @ p1_w                       (43520 x 64, K=256)
    gemm_kernel<0><<<dim3(1, (BS * TOTALPIX) / 64), t>>>(memory, p1_w, nullptr, proj,
                                                         BS * TOTALPIX, 64, 256);
    // X rows via roi_align on projected memory
    build_x_kernel<<<NROWS, 256>>>(ref, p1_b);
    // MLP chain
    gemm_kernel<1><<<dim3(256 / 64, cdiv(NROWS, 64)), t>>>(X,  w1, b1, H1, NROWS, 256, XCOLS);
    gemm_kernel<1><<<dim3(512 / 64, cdiv(NROWS, 64)), t>>>(H1, w2, b2, H2, NROWS, 512, 256);
    gemm_kernel<1><<<dim3(512 / 64, cdiv(NROWS, 64)), t>>>(H2, w3, b3, H3, NROWS, 512, 512);
    gemm_kernel<3><<<dim3(1,        cdiv(NROWS, 64)), t>>>(H3, w4, b4, pts, NROWS, 16, 512);
    // grid-sample recompute + gate + softmax combine
    finalize_kernel<<<BQ, 256>>>(memory, ref, a2w, a2b, out);
}

// round 2
// speedup vs baseline: 1.0404x; 1.0404x over previous
#include <cuda_runtime.h>
#include <cuda_bf16.h>
#include <math.h>
#include <stdint.h>

#define HIDDEN   256
#define NQ       300
#define BS       2
#define LVLS     4
#define NHEADS   8
#define TOTALPIX 21760
#define BQ       (BS*NQ)          // 600
#define NROWS    (LVLS*BS*NQ)     // 2400
#define XCOLS    3136

// ---------------- scratch (static device globals; no runtime alloc) ----------
__device__ float g_gate[BQ * NHEADS * HIDDEN];   // 600 x 2048
__device__ float g_proj[BS * TOTALPIX * 64];     // projected memory
__device__ float g_X  [NROWS * XCOLS];           // MLP input rows
__device__ float g_H1 [NROWS * 256];
__device__ float g_H2 [NROWS * 512];
__device__ float g_H3 [NROWS * 512];
__device__ float g_pts[NROWS * 16];

__device__ __constant__ int c_dim[4]   = {128, 64, 32, 16};
__device__ __constant__ int c_start[4] = {0, 16384, 20480, 21504};

// ---------------- shared geometry helper (roi_align sampling) ----------------
__device__ __forceinline__ void sample4(float sx, float sy, float bw, float bh,
                                        int W, int si, int sj,
                                        int idx[4], float wt[4]) {
    float Wf = (float)W;
    float ty = (float)(si >> 1) + 0.25f + 0.5f * (float)(si & 1);
    float tx = (float)(sj >> 1) + 0.25f + 0.5f * (float)(sj & 1);
    float y = sy + bh * ty;
    float x = sx + bw * tx;
    bool valid = (y >= -1.f) && (y <= Wf) && (x >= -1.f) && (x <= Wf);
    float yc = fminf(fmaxf(y, 0.f), Wf - 1.f);
    float xc = fminf(fmaxf(x, 0.f), Wf - 1.f);
    float y0 = fminf(floorf(yc), Wf - 2.f);
    float x0 = fminf(floorf(xc), Wf - 2.f);
    float ly = yc - y0, lx = xc - x0;
    int yi = (int)y0, xi = (int)x0;
    int p = yi * W + xi;
    float vm = valid ? 0.25f : 0.f;
    float oy = 1.f - ly, ox = 1.f - lx;
    idx[0] = p;         wt[0] = oy * ox * vm;
    idx[1] = p + 1;     wt[1] = oy * lx * vm;
    idx[2] = p + W;     wt[2] = ly * ox * vm;
    idx[3] = p + W + 1; wt[3] = ly * lx * vm;
}

__device__ __forceinline__ void box_geom(const float* __restrict__ r6, int W,
                                         float& sx, float& sy, float& bw, float& bh) {
    float Wf = (float)W;
    float cx = r6[0], cy = r6[1];
    float x1 = fminf(fmaxf(cx - r6[2], 0.f), 1.f) * Wf;
    float y1 = fminf(fmaxf(cy - r6[3], 0.f), 1.f) * Wf;
    float x2 = fminf(fmaxf(cx + r6[4], 0.f), 1.f) * Wf;
    float y2 = fminf(fmaxf(cy + r6[5], 0.f), 1.f) * Wf;
    sx = x1 - 0.5f; sy = y1 - 0.5f;
    bw = (x2 - x1) / 7.f; bh = (y2 - y1) / 7.f;
}

// ---------------- tf32 tensor-core GEMM ---------------------------------------
// C = epi(A(MxK) @ B(KxN) + bias).  BM in {64,128}, BN=64, BK=16, 256 threads.
// Warp grid 4(m) x 2(n); warp tile (BM/4) x 32; fragments m16n8k8.
// PREC=1: single tf32 pass. PREC=3: 3xTF32 split precision (~fp32 accuracy).
// K must be a multiple of 16 (all call sites satisfy this).

__device__ __forceinline__ uint32_t f2tf(float x) {
    uint32_t u; asm("cvt.rna.tf32.f32 %0, %1;" : "=r"(u) : "f"(x)); return u;
}

__device__ __forceinline__ void mma_tf32(float c[4], const uint32_t a[4], const uint32_t b[2]) {
    asm volatile(
        "mma.sync.aligned.m16n8k8.row.col.f32.tf32.tf32.f32 "
        "{%0,%1,%2,%3},{%4,%5,%6,%7},{%8,%9},{%0,%1,%2,%3};"
        : "+f"(c[0]), "+f"(c[1]), "+f"(c[2]), "+f"(c[3])
        : "r"(a[0]), "r"(a[1]), "r"(a[2]), "r"(a[3]), "r"(b[0]), "r"(b[1]));
}

template <int EPI, int PREC, int BM>   // EPI: 0 none, 1 relu, 2 sigmoid, 3 tanh
__global__ __launch_bounds__(256)
void tc_gemm(const float* __restrict__ A, const float* __restrict__ B,
             const float* __restrict__ bias, float* __restrict__ C,
             int M, int N, int K) {
    constexpr int MF = BM / 64;              // m16 fragments per warp in m
    __shared__ float As[BM][20];             // [m][k], padded
    __shared__ float Bs[16][72];             // [k][n], padded

    int bn0 = blockIdx.x * 64, bm0 = blockIdx.y * BM;
    int tid  = threadIdx.x;
    int warp = tid >> 5, lane = tid & 31;
    int wm0 = (warp & 3) * (BM / 4);         // warp m offset in tile
    int wn0 = (warp >> 2) * 32;              // warp n offset in tile
    int lq  = lane >> 2;                     // 0..7
    int lr  = lane & 3;                      // 0..3

    float acc[MF][4][4];
#pragma unroll
    for (int i = 0; i < MF; i++)
#pragma unroll
        for (int j = 0; j < 4; j++)
#pragma unroll
            for (int k = 0; k < 4; k++) acc[i][j][k] = 0.f;

    for (int k0 = 0; k0 < K; k0 += 16) {
        // load A tile (BM x 16)
#pragma unroll
        for (int e = tid; e < BM * 4; e += 256) {
            int row = e >> 2, kq = (e & 3) * 4;
            float4 v = make_float4(0.f, 0.f, 0.f, 0.f);
            if (bm0 + row < M)
                v = *(const float4*)(A + (size_t)(bm0 + row) * K + k0 + kq);
            As[row][kq + 0] = v.x; As[row][kq + 1] = v.y;
            As[row][kq + 2] = v.z; As[row][kq + 3] = v.w;
        }
        // load B tile (16 x 64)
        {
            int row = tid >> 4, nq = (tid & 15) * 4;
            float4 v = make_float4(0.f, 0.f, 0.f, 0.f);
            if (bn0 + nq < N)
                v = *(const float4*)(B + (size_t)(k0 + row) * N + bn0 + nq);
            *(float4*)&Bs[row][nq] = v;
        }
        __syncthreads();

#pragma unroll
        for (int ks = 0; ks < 2; ks++) {
            int kb = ks * 8;
            uint32_t aHi[MF][4], aLo[MF][4];
#pragma unroll
            for (int mf = 0; mf < MF; mf++)
#pragma unroll
                for (int r = 0; r < 4; r++) {
                    int row = wm0 + mf * 16 + lq + ((r & 1) ? 8 : 0);
                    int col = kb + lr + ((r >= 2) ? 4 : 0);
                    float v = As[row][col];
                    uint32_t h = f2tf(v);
                    aHi[mf][r] = h;
                    if (PREC == 3) aLo[mf][r] = f2tf(v - __uint_as_float(h));
                }
            uint32_t bHi[4][2], bLo[4][2];
#pragma unroll
            for (int nf = 0; nf < 4; nf++)
#pragma unroll
                for (int r = 0; r < 2; r++) {
                    float v = Bs[kb + lr + r * 4][wn0 + nf * 8 + lq];
                    uint32_t h = f2tf(v);
                    bHi[nf][r] = h;
                    if (PREC == 3) bLo[nf][r] = f2tf(v - __uint_as_float(h));
                }
#pragma unroll
            for (int mf = 0; mf < MF; mf++)
#pragma unroll
                for (int nf = 0; nf < 4; nf++) {
                    if (PREC == 3) {
                        mma_tf32(acc[mf][nf], aLo[mf], bHi[nf]);
                        mma_tf32(acc[mf][nf], aHi[mf], bLo[nf]);
                    }
                    mma_tf32(acc[mf][nf], aHi[mf], bHi[nf]);
                }
        }
        __syncthreads();
    }

    // epilogue
#pragma unroll
    for (int mf = 0; mf < MF; mf++)
#pragma unroll
        for (int nf = 0; nf < 4; nf++)
#pragma unroll
            for (int ci = 0; ci < 4; ci++) {
                int m = bm0 + wm0 + mf * 16 + lq + ((ci >= 2) ? 8 : 0);
                int n = bn0 + wn0 + nf * 8 + lr * 2 + (ci & 1);
                if (m >= M || n >= N) continue;
                float v = acc[mf][nf][ci] + (bias ? bias[n] : 0.f);
                if (EPI == 1) v = fmaxf(v, 0.f);
                else if (EPI == 2) v = 1.f / (1.f + expf(-v));
                else if (EPI == 3) v = tanhf(v);
                C[(size_t)m * N + n] = v;
            }
}

// ---------------- build X rows: relu(roi_align(proj) + p1_b), flattened ------
__global__ __launch_bounds__(256)
void build_x_kernel(const float* __restrict__ ref, const float* __restrict__ p1_b) {
    int blk = blockIdx.x;                 // lvl*600 + b*300 + q
    int lvl = blk / BQ;
    int rem = blk - lvl * BQ;
    int b = rem / NQ;
    int q = rem - b * NQ;
    int W = c_dim[lvl];
    int start = c_start[lvl];
    const float* r6 = ref + ((size_t)(b * NQ + q) * LVLS + lvl) * 6;
    float sx, sy, bw, bh;
    box_geom(r6, W, sx, sy, bw, bh);

    __shared__ int   sIdx[196][4];
    __shared__ float sW[196][4];
    int tid = threadIdx.x;
    if (tid < 196) {
        int si = tid / 14, sj = tid - si * 14;
        int idx4[4]; float wt4[4];
        sample4(sx, sy, bw, bh, W, si, sj, idx4, wt4);
#pragma unroll
        for (int k = 0; k < 4; k++) { sIdx[tid][k] = idx4[k]; sW[tid][k] = wt4[k]; }
    }
    __syncthreads();

    int d = tid & 63;
    int g = tid >> 6;                      // 0..3
    const float* projB = g_proj + ((size_t)b * TOTALPIX + start) * 64 + d;
    float bias = p1_b[d];
    float* Xrow = g_X + (size_t)blk * XCOLS + d * 49;
    for (int bin = g; bin < 49; bin += 4) {
        int h = bin / 7, w_ = bin - h * 7;
        float acc = 0.f;
#pragma unroll
        for (int s2 = 0; s2 < 4; s2++) {
            int s = (2 * h + (s2 >> 1)) * 14 + 2 * w_ + (s2 & 1);
#pragma unroll
            for (int cr = 0; cr < 4; cr++)
                acc += sW[s][cr] * projB[(size_t)sIdx[s][cr] * 64];
        }
        Xrow[bin] = fmaxf(acc + bias, 0.f);
    }
}

// ---------------- finalize: grid_sample recompute + gate + softmax combine ---
__global__ __launch_bounds__(256)
void finalize_kernel(const float* __restrict__ memory, const float* __restrict__ ref,
                     const float* __restrict__ a2w, const float* __restrict__ a2b,
                     float* __restrict__ out) {
    int bq = blockIdx.x;                   // b*300 + q
    int b = bq / NQ;
    int tid = threadIdx.x;

    __shared__ float qe_s[32][HIDDEN];     // 32 KB
    __shared__ float wArr[2048];           // 8 KB
    __shared__ unsigned short iArr[2048];  // 4 KB (pixel index < 43520)
    __shared__ float logits[32];
    __shared__ float wgt[32];

    for (int e = tid; e < 2048; e += 256) {
        int lvl = e >> 9;
        int head = (e >> 6) & 7;
        int bc = (e >> 4) & 3;
        int sm = (e >> 2) & 3;
        int cr = e & 3;
        int W = c_dim[lvl];
        int start = c_start[lvl];
        const float* r6 = ref + ((size_t)bq * LVLS + lvl) * 6;
        float sx, sy, bw, bh;
        box_geom(r6, W, sx, sy, bw, bh);

        int row = lvl * BQ + bq;
        float gx = g_pts[row * 16 + 2 * head];
        float gy = g_pts[row * 16 + 2 * head + 1];
        float ix = ((gx + 1.f) * 7.f - 1.f) * 0.5f;
        float iy = ((gy + 1.f) * 7.f - 1.f) * 0.5f;
        float bxf = floorf(ix), byf = floorf(iy);
        float lx = ix - bxf, ly = iy - byf;
        int dby = bc >> 1, dbx = bc & 1;
        int bi = (int)byf + dby, bj = (int)bxf + dbx;
        float wb = (dby ? ly : 1.f - ly) * (dbx ? lx : 1.f - lx);
        if (bi < 0 || bi > 6 || bj < 0 || bj > 6) wb = 0.f;
        int si = 2 * bi + (sm >> 1);
        int sj = 2 * bj + (sm & 1);
        int idx4[4]; float wt4[4];
        sample4(sx, sy, bw, bh, W, si, sj, idx4, wt4);
        wArr[e] = wb * wt4[cr];
        iArr[e] = (unsigned short)(b * TOTALPIX + start + idx4[cr]);
    }
    __syncthreads();

    const float* gateRow = g_gate + (size_t)bq * (NHEADS * HIDDEN);
    int c = tid;
    for (int lh = 0; lh < 32; lh++) {
        float a0 = 0.f, a1 = 0.f, a2 = 0.f, a3 = 0.f;
        int eb = lh << 6;
#pragma unroll 4
        for (int e = 0; e < 64; e += 4) {
            float w0 = wArr[eb + e + 0];
            float w1 = wArr[eb + e + 1];
            float w2 = wArr[eb + e + 2];
            float w3 = wArr[eb + e + 3];
            if (w0 != 0.f) a0 += w0 * memory[(size_t)iArr[eb + e + 0] * HIDDEN + c];
            if (w1 != 0.f) a1 += w1 * memory[(size_t)iArr[eb + e + 1] * HIDDEN + c];
            if (w2 != 0.f) a2 += w2 * memory[(size_t)iArr[eb + e + 2] * HIDDEN + c];
            if (w3 != 0.f) a3 += w3 * memory[(size_t)iArr[eb + e + 3] * HIDDEN + c];
        }
        qe_s[lh][c] = ((a0 + a1) + (a2 + a3)) * gateRow[(lh & 7) * HIDDEN + c];
    }
    __syncthreads();

    int warp = tid >> 5, lane = tid & 31;
    for (int r = warp; r < 32; r += 8) {
        float s = 0.f;
#pragma unroll
        for (int c2 = lane; c2 < HIDDEN; c2 += 32) s += qe_s[r][c2] * a2w[c2];
#pragma unroll
        for (int o = 16; o; o >>= 1) s += __shfl_xor_sync(0xffffffffu, s, o);
        if (lane == 0) logits[r] = s + a2b[0];
    }
    __syncthreads();

    if (tid < 32) {
        float l = logits[tid];
        float mx = l;
#pragma unroll
        for (int o = 16; o; o >>= 1) mx = fmaxf(mx, __shfl_xor_sync(0xffffffffu, mx, o));
        float ex = expf(l - mx);
        float sum = ex;
#pragma unroll
        for (int o = 16; o; o >>= 1) sum += __shfl_xor_sync(0xffffffffu, sum, o);
        wgt[tid] = ex / sum;
    }
    __syncthreads();

    float o = 0.f;
#pragma unroll
    for (int r = 0; r < 32; r++) o += wgt[r] * qe_s[r][c];
    out[(size_t)bq * HIDDEN + c] = o;
}

// -----------------------------------------------------------------------------
static inline int cdiv(int a, int b) { return (a + b - 1) / b; }

extern "C" void kernel_launch(void* const* d_in, const int* in_sizes, int n_in,
                              void* d_out, int out_size) {
    const float* tgt    = (const float*)d_in[0];
    const float* memory = (const float*)d_in[1];
    const float* ref    = (const float*)d_in[2];
    const float* p1_w = (const float*)d_in[4];
    const float* p1_b = (const float*)d_in[5];
    const float* w1   = (const float*)d_in[6];
    const float* b1   = (const float*)d_in[7];
    const float* w2   = (const float*)d_in[8];
    const float* b2   = (const float*)d_in[9];
    const float* w3   = (const float*)d_in[10];
    const float* b3   = (const float*)d_in[11];
    const float* w4   = (const float*)d_in[12];
    const float* b4   = (const float*)d_in[13];
    const float* a1w  = (const float*)d_in[14];
    const float* a1b  = (const float*)d_in[15];
    const float* a2w  = (const float*)d_in[16];
    const float* a2b  = (const float*)d_in[17];
    float* out = (float*)d_out;

    float *gate, *proj, *X, *H1, *H2, *H3, *pts;
    cudaGetSymbolAddress((void**)&gate, g_gate);
    cudaGetSymbolAddress((void**)&proj, g_proj);
    cudaGetSymbolAddress((void**)&X,    g_X);
    cudaGetSymbolAddress((void**)&H1,   g_H1);
    cudaGetSymbolAddress((void**)&H2,   g_H2);
    cudaGetSymbolAddress((void**)&H3,   g_H3);
    cudaGetSymbolAddress((void**)&pts,  g_pts);

    dim3 t(256);
    // gate = sigmoid(tgt @ attn1_w + attn1_b)   (600 x 2048, K=256)
    tc_gemm<2, 3, 128><<<dim3(2048 / 64, cdiv(BQ, 128)), t>>>(tgt, a1w, a1b, gate, BQ, 2048, 256);
    // proj = memory @ p1_w                       (43520 x 64, K=256)
    tc_gemm<0, 3, 128><<<dim3(1, (BS * TOTALPIX) / 128), t>>>(memory, p1_w, nullptr, proj,
                                                              BS * TOTALPIX, 64, 256);
    // X rows via roi_align on projected memory
    build_x_kernel<<<NROWS, 256>>>(ref, p1_b);
    // MLP chain
    tc_gemm<1, 3, 64 ><<<dim3(256 / 64, cdiv(NROWS, 64)),  t>>>(X,  w1, b1, H1, NROWS, 256, XCOLS);
    tc_gemm<1, 3, 128><<<dim3(512 / 64, cdiv(NROWS, 128)), t>>>(H1, w2, b2, H2, NROWS, 512, 256);
    tc_gemm<1, 3, 128><<<dim3(512 / 64, cdiv(NROWS, 128)), t>>>(H2, w3, b3, H3, NROWS, 512, 512);
    tc_gemm<3, 3, 64 ><<<dim3(1,        cdiv(NROWS, 64)),  t>>>(H3, w4, b4, pts, NROWS, 16, 512);
    // grid-sample recompute + gate + softmax combine
    finalize_kernel<<<BQ, 256>>>(memory, ref, a2w, a2b, out);
}

// round 3
// speedup vs baseline: 1.2351x; 1.1871x over previous
#include <cuda_runtime.h>
#include <cuda_bf16.h>
#include <math.h>
#include <stdint.h>

#define HIDDEN   256
#define NQ       300
#define BS       2
#define LVLS     4
#define NHEADS   8
#define TOTALPIX 21760
#define BQ       (BS*NQ)          // 600
#define NROWS    (LVLS*BS*NQ)     // 2400
#define XCOLS    3136

// ---------------- scratch (static device globals; no runtime alloc) ----------
__device__ float g_gate[BQ * NHEADS * HIDDEN];   // 600 x 2048
__device__ float g_proj[BS * TOTALPIX * 64];     // projected memory
__device__ float g_X  [NROWS * XCOLS];           // MLP input rows
__device__ float g_P  [2 * NROWS * 256];         // split-K partials
__device__ float g_H1 [NROWS * 256];
__device__ float g_H2 [NROWS * 512];
__device__ float g_H3 [NROWS * 512];
__device__ float g_pts[NROWS * 16];

__device__ __constant__ int c_dim[4]   = {128, 64, 32, 16};
__device__ __constant__ int c_start[4] = {0, 16384, 20480, 21504};

// ---------------- shared geometry helper (roi_align sampling) ----------------
__device__ __forceinline__ void sample4(float sx, float sy, float bw, float bh,
                                        int W, int si, int sj,
                                        int idx[4], float wt[4]) {
    float Wf = (float)W;
    float ty = (float)(si >> 1) + 0.25f + 0.5f * (float)(si & 1);
    float tx = (float)(sj >> 1) + 0.25f + 0.5f * (float)(sj & 1);
    float y = sy + bh * ty;
    float x = sx + bw * tx;
    bool valid = (y >= -1.f) && (y <= Wf) && (x >= -1.f) && (x <= Wf);
    float yc = fminf(fmaxf(y, 0.f), Wf - 1.f);
    float xc = fminf(fmaxf(x, 0.f), Wf - 1.f);
    float y0 = fminf(floorf(yc), Wf - 2.f);
    float x0 = fminf(floorf(xc), Wf - 2.f);
    float ly = yc - y0, lx = xc - x0;
    int yi = (int)y0, xi = (int)x0;
    int p = yi * W + xi;
    float vm = valid ? 0.25f : 0.f;
    float oy = 1.f - ly, ox = 1.f - lx;
    idx[0] = p;         wt[0] = oy * ox * vm;
    idx[1] = p + 1;     wt[1] = oy * lx * vm;
    idx[2] = p + W;     wt[2] = ly * ox * vm;
    idx[3] = p + W + 1; wt[3] = ly * lx * vm;
}

__device__ __forceinline__ void box_geom(const float* __restrict__ r6, int W,
                                         float& sx, float& sy, float& bw, float& bh) {
    float Wf = (float)W;
    float cx = r6[0], cy = r6[1];
    float x1 = fminf(fmaxf(cx - r6[2], 0.f), 1.f) * Wf;
    float y1 = fminf(fmaxf(cy - r6[3], 0.f), 1.f) * Wf;
    float x2 = fminf(fmaxf(cx + r6[4], 0.f), 1.f) * Wf;
    float y2 = fminf(fmaxf(cy + r6[5], 0.f), 1.f) * Wf;
    sx = x1 - 0.5f; sy = y1 - 0.5f;
    bw = (x2 - x1) / 7.f; bh = (y2 - y1) / 7.f;
}

// ---------------- tf32 tensor-core GEMM (3xTF32 split precision) --------------
// C = epi(A(MxK) @ B(KxN) + bias).  BM=BN=64, BK=32, 256 threads.
// Warps 4(m) x 2(n); warp tile 16x32; fragments m16n8k8.
// hi/lo tf32 split computed ONCE at SMEM store time, stored as float2{hi,lo}.
// gridDim.z = split-K slabs: slab z covers k in [z*kSplit, (z+1)*kSplit) and
// writes to C + z*M*N. K (and kSplit) must be multiples of 32.

__device__ __forceinline__ uint32_t f2tf(float x) {
    uint32_t u; asm("cvt.rna.tf32.f32 %0, %1;" : "=r"(u) : "f"(x)); return u;
}
__device__ __forceinline__ float2 tfsplit(float v) {
    uint32_t h = f2tf(v);
    uint32_t l = f2tf(v - __uint_as_float(h));
    return make_float2(__uint_as_float(h), __uint_as_float(l));
}

__device__ __forceinline__ void mma_tf32(float c[4], const uint32_t a[4], const uint32_t b[2]) {
    asm volatile(
        "mma.sync.aligned.m16n8k8.row.col.f32.tf32.tf32.f32 "
        "{%0,%1,%2,%3},{%4,%5,%6,%7},{%8,%9},{%0,%1,%2,%3};"
        : "+f"(c[0]), "+f"(c[1]), "+f"(c[2]), "+f"(c[3])
        : "r"(a[0]), "r"(a[1]), "r"(a[2]), "r"(a[3]), "r"(b[0]), "r"(b[1]));
}

template <int EPI>   // 0 none, 1 relu, 2 sigmoid, 3 tanh
__global__ __launch_bounds__(256, 3)
void tc_gemm(const float* __restrict__ A, const float* __restrict__ B,
             const float* __restrict__ bias, float* __restrict__ C,
             int M, int N, int K, int kSplit) {
    __shared__ float2 As[64][36];   // [m][k] {hi,lo}, stride 36 -> conflict-free
    __shared__ float2 Bs[32][72];   // [k][n] {hi,lo}, stride 72 -> conflict-free

    int bn0 = blockIdx.x * 64, bm0 = blockIdx.y * 64;
    int kS = blockIdx.z * kSplit;
    C += (size_t)blockIdx.z * M * N;

    int tid  = threadIdx.x;
    int warp = tid >> 5, lane = tid & 31;
    int wm0 = (warp & 3) * 16;
    int wn0 = (warp >> 2) * 32;
    int lq  = lane >> 2;            // 0..7
    int lr  = lane & 3;             // 0..3

    // load indices
    int aM0 = tid >> 3,          aK0 = (tid & 7) * 4;      // + t*32 rows
    int bK0 = tid >> 4,          bN0 = (tid & 15) * 4;     // + t*16 rows

    float acc[4][4];
#pragma unroll
    for (int j = 0; j < 4; j++)
#pragma unroll
        for (int k = 0; k < 4; k++) acc[j][k] = 0.f;

    float4 aReg[2], bReg[2];
    // prologue: load tile 0
#pragma unroll
    for (int t = 0; t < 2; t++) {
        int m = aM0 + t * 32;
        aReg[t] = (bm0 + m < M) ? *(const float4*)(A + (size_t)(bm0 + m) * K + kS + aK0)
                                : make_float4(0.f, 0.f, 0.f, 0.f);
        int kk = bK0 + t * 16;
        bReg[t] = (bn0 + bN0 < N) ? *(const float4*)(B + (size_t)(kS + kk) * N + bn0 + bN0)
                                  : make_float4(0.f, 0.f, 0.f, 0.f);
    }

    int T = kSplit / 32;
    for (int t = 0; t < T; t++) {
        // store current tile (with tf32 split)
#pragma unroll
        for (int u = 0; u < 2; u++) {
            float2* da = &As[aM0 + u * 32][aK0];
            da[0] = tfsplit(aReg[u].x); da[1] = tfsplit(aReg[u].y);
            da[2] = tfsplit(aReg[u].z); da[3] = tfsplit(aReg[u].w);
            float2* db = &Bs[bK0 + u * 16][bN0];
            db[0] = tfsplit(bReg[u].x); db[1] = tfsplit(bReg[u].y);
            db[2] = tfsplit(bReg[u].z); db[3] = tfsplit(bReg[u].w);
        }
        __syncthreads();

        // prefetch next tile
        if (t + 1 < T) {
            int k0 = kS + (t + 1) * 32;
#pragma unroll
            for (int u = 0; u < 2; u++) {
                int m = aM0 + u * 32;
                aReg[u] = (bm0 + m < M) ? *(const float4*)(A + (size_t)(bm0 + m) * K + k0 + aK0)
                                        : make_float4(0.f, 0.f, 0.f, 0.f);
                int kk = bK0 + u * 16;
                bReg[u] = (bn0 + bN0 < N) ? *(const float4*)(B + (size_t)(k0 + kk) * N + bn0 + bN0)
                                          : make_float4(0.f, 0.f, 0.f, 0.f);
            }
        }

        // compute
#pragma unroll
        for (int kb = 0; kb < 32; kb += 8) {
            uint32_t aH[4], aL[4];
#pragma unroll
            for (int r = 0; r < 4; r++) {
                float2 v = As[wm0 + lq + ((r & 1) << 3)][kb + lr + ((r & 2) << 1)];
                aH[r] = __float_as_uint(v.x);
                aL[r] = __float_as_uint(v.y);
            }
            uint32_t bH[4][2], bL[4][2];
#pragma unroll
            for (int nf = 0; nf < 4; nf++)
#pragma unroll
                for (int r = 0; r < 2; r++) {
                    float2 v = Bs[kb + lr + (r << 2)][wn0 + nf * 8 + lq];
                    bH[nf][r] = __float_as_uint(v.x);
                    bL[nf][r] = __float_as_uint(v.y);
                }
#pragma unroll
            for (int nf = 0; nf < 4; nf++) {
                mma_tf32(acc[nf], aL, bH[nf]);
                mma_tf32(acc[nf], aH, bL[nf]);
                mma_tf32(acc[nf], aH, bH[nf]);
            }
        }
        __syncthreads();
    }

    // epilogue
#pragma unroll
    for (int nf = 0; nf < 4; nf++)
#pragma unroll
        for (int ci = 0; ci < 4; ci++) {
            int m = bm0 + wm0 + lq + ((ci >= 2) ? 8 : 0);
            int n = bn0 + wn0 + nf * 8 + lr * 2 + (ci & 1);
            if (m >= M || n >= N) continue;
            float v = acc[nf][ci] + (bias ? bias[n] : 0.f);
            if (EPI == 1) v = fmaxf(v, 0.f);
            else if (EPI == 2) v = 1.f / (1.f + expf(-v));
            else if (EPI == 3) v = tanhf(v);
            C[(size_t)m * N + n] = v;
        }
}

// ---------------- split-K combine: H1 = relu(P0 + P1 + b1) -------------------
__global__ __launch_bounds__(256)
void relu_combine_kernel(const float* __restrict__ P, const float* __restrict__ bias,
                         float* __restrict__ H) {
    int i = blockIdx.x * 256 + threadIdx.x;
    if (i < NROWS * 256) {
        float v = P[i] + P[i + NROWS * 256] + bias[i & 255];
        H[i] = fmaxf(v, 0.f);
    }
}

// ---------------- build X rows: relu(roi_align(proj) + p1_b), flattened ------
__global__ __launch_bounds__(256)
void build_x_kernel(const float* __restrict__ ref, const float* __restrict__ p1_b) {
    int blk = blockIdx.x;                 // lvl*600 + b*300 + q
    int lvl = blk / BQ;
    int rem = blk - lvl * BQ;
    int b = rem / NQ;
    int q = rem - b * NQ;
    int W = c_dim[lvl];
    int start = c_start[lvl];
    const float* r6 = ref + ((size_t)(b * NQ + q) * LVLS + lvl) * 6;
    float sx, sy, bw, bh;
    box_geom(r6, W, sx, sy, bw, bh);

    __shared__ int   sIdx[196][4];
    __shared__ float sW[196][4];
    int tid = threadIdx.x;
    if (tid < 196) {
        int si = tid / 14, sj = tid - si * 14;
        int idx4[4]; float wt4[4];
        sample4(sx, sy, bw, bh, W, si, sj, idx4, wt4);
#pragma unroll
        for (int k = 0; k < 4; k++) { sIdx[tid][k] = idx4[k]; sW[tid][k] = wt4[k]; }
    }
    __syncthreads();

    int d = tid & 63;
    int g = tid >> 6;                      // 0..3
    const float* projB = g_proj + ((size_t)b * TOTALPIX + start) * 64 + d;
    float bias = p1_b[d];
    float* Xrow = g_X + (size_t)blk * XCOLS + d * 49;
    for (int bin = g; bin < 49; bin += 4) {
        int h = bin / 7, w_ = bin - h * 7;
        float acc = 0.f;
#pragma unroll
        for (int s2 = 0; s2 < 4; s2++) {
            int s = (2 * h + (s2 >> 1)) * 14 + 2 * w_ + (s2 & 1);
#pragma unroll
            for (int cr = 0; cr < 4; cr++)
                acc += sW[s][cr] * projB[(size_t)sIdx[s][cr] * 64];
        }
        Xrow[bin] = fmaxf(acc + bias, 0.f);
    }
}

// ---------------- finalize: grid_sample recompute + gate + softmax combine ---
__global__ __launch_bounds__(256)
void finalize_kernel(const float* __restrict__ memory, const float* __restrict__ ref,
                     const float* __restrict__ a2w, const float* __restrict__ a2b,
                     float* __restrict__ out) {
    int bq = blockIdx.x;                   // b*300 + q
    int b = bq / NQ;
    int tid = threadIdx.x;

    __shared__ float qe_s[32][HIDDEN];     // 32 KB
    __shared__ float wArr[2048];           // 8 KB
    __shared__ unsigned short iArr[2048];  // 4 KB
    __shared__ float logits[32];
    __shared__ float wgt[32];

    for (int e = tid; e < 2048; e += 256) {
        int lvl = e >> 9;
        int head = (e >> 6) & 7;
        int bc = (e >> 4) & 3;
        int sm = (e >> 2) & 3;
        int cr = e & 3;
        int W = c_dim[lvl];
        int start = c_start[lvl];
        const float* r6 = ref + ((size_t)bq * LVLS + lvl) * 6;
        float sx, sy, bw, bh;
        box_geom(r6, W, sx, sy, bw, bh);

        int row = lvl * BQ + bq;
        float gx = g_pts[row * 16 + 2 * head];
        float gy = g_pts[row * 16 + 2 * head + 1];
        float ix = ((gx + 1.f) * 7.f - 1.f) * 0.5f;
        float iy = ((gy + 1.f) * 7.f - 1.f) * 0.5f;
        float bxf = floorf(ix), byf = floorf(iy);
        float lx = ix - bxf, ly = iy - byf;
        int dby = bc >> 1, dbx = bc & 1;
        int bi = (int)byf + dby, bj = (int)bxf + dbx;
        float wb = (dby ? ly : 1.f - ly) * (dbx ? lx : 1.f - lx);
        if (bi < 0 || bi > 6 || bj < 0 || bj > 6) wb = 0.f;
        int si = 2 * bi + (sm >> 1);
        int sj = 2 * bj + (sm & 1);
        int idx4[4]; float wt4[4];
        sample4(sx, sy, bw, bh, W, si, sj, idx4, wt4);
        wArr[e] = wb * wt4[cr];
        iArr[e] = (unsigned short)(b * TOTALPIX + start + idx4[cr]);
    }
    __syncthreads();

    const float* gateRow = g_gate + (size_t)bq * (NHEADS * HIDDEN);
    int c = tid;
    for (int lh = 0; lh < 32; lh++) {
        float a0 = 0.f, a1 = 0.f, a2 = 0.f, a3 = 0.f;
        int eb = lh << 6;
#pragma unroll 4
        for (int e = 0; e < 64; e += 4) {
            float w0 = wArr[eb + e + 0];
            float w1 = wArr[eb + e + 1];
            float w2 = wArr[eb + e + 2];
            float w3 = wArr[eb + e + 3];
            if (w0 != 0.f) a0 += w0 * memory[(size_t)iArr[eb + e + 0] * HIDDEN + c];
            if (w1 != 0.f) a1 += w1 * memory[(size_t)iArr[eb + e + 1] * HIDDEN + c];
            if (w2 != 0.f) a2 += w2 * memory[(size_t)iArr[eb + e + 2] * HIDDEN + c];
            if (w3 != 0.f) a3 += w3 * memory[(size_t)iArr[eb + e + 3] * HIDDEN + c];
        }
        qe_s[lh][c] = ((a0 + a1) + (a2 + a3)) * gateRow[(lh & 7) * HIDDEN + c];
    }
    __syncthreads();

    int warp = tid >> 5, lane = tid & 31;
    for (int r = warp; r < 32; r += 8) {
        float s = 0.f;
#pragma unroll
        for (int c2 = lane; c2 < HIDDEN; c2 += 32) s += qe_s[r][c2] * a2w[c2];
#pragma unroll
        for (int o = 16; o; o >>= 1) s += __shfl_xor_sync(0xffffffffu, s, o);
        if (lane == 0) logits[r] = s + a2b[0];
    }
    __syncthreads();

    if (tid < 32) {
        float l = logits[tid];
        float mx = l;
#pragma unroll
        for (int o = 16; o; o >>= 1) mx = fmaxf(mx, __shfl_xor_sync(0xffffffffu, mx, o));
        float ex = expf(l - mx);
        float sum = ex;
#pragma unroll
        for (int o = 16; o; o >>= 1) sum += __shfl_xor_sync(0xffffffffu, sum, o);
        wgt[tid] = ex / sum;
    }
    __syncthreads();

    float o = 0.f;
#pragma unroll
    for (int r = 0; r < 32; r++) o += wgt[r] * qe_s[r][c];
    out[(size_t)bq * HIDDEN + c] = o;
}

// -----------------------------------------------------------------------------
static inline int cdiv(int a, int b) { return (a + b - 1) / b; }

extern "C" void kernel_launch(void* const* d_in, const int* in_sizes, int n_in,
                              void* d_out, int out_size) {
    const float* tgt    = (const float*)d_in[0];
    const float* memory = (const float*)d_in[1];
    const float* ref    = (const float*)d_in[2];
    const float* p1_w = (const float*)d_in[4];
    const float* p1_b = (const float*)d_in[5];
    const float* w1   = (const float*)d_in[6];
    const float* b1   = (const float*)d_in[7];
    const float* w2   = (const float*)d_in[8];
    const float* b2   = (const float*)d_in[9];
    const float* w3   = (const float*)d_in[10];
    const float* b3   = (const float*)d_in[11];
    const float* w4   = (const float*)d_in[12];
    const float* b4   = (const float*)d_in[13];
    const float* a1w  = (const float*)d_in[14];
    const float* a1b  = (const float*)d_in[15];
    const float* a2w  = (const float*)d_in[16];
    const float* a2b  = (const float*)d_in[17];
    float* out = (float*)d_out;

    float *gate, *proj, *X, *P, *H1, *H2, *H3, *pts;
    cudaGetSymbolAddress((void**)&gate, g_gate);
    cudaGetSymbolAddress((void**)&proj, g_proj);
    cudaGetSymbolAddress((void**)&X,    g_X);
    cudaGetSymbolAddress((void**)&P,    g_P);
    cudaGetSymbolAddress((void**)&H1,   g_H1);
    cudaGetSymbolAddress((void**)&H2,   g_H2);
    cudaGetSymbolAddress((void**)&H3,   g_H3);
    cudaGetSymbolAddress((void**)&pts,  g_pts);

    dim3 t(256);
    // gate = sigmoid(tgt @ attn1_w + attn1_b)   (600 x 2048, K=256)
    tc_gemm<2><<<dim3(32, 10, 1), t>>>(tgt, a1w, a1b, gate, BQ, 2048, 256, 256);
    // proj = memory @ p1_w                       (43520 x 64, K=256)
    tc_gemm<0><<<dim3(1, 680, 1), t>>>(memory, p1_w, nullptr, proj, BS * TOTALPIX, 64, 256, 256);
    // X rows via roi_align on projected memory
    build_x_kernel<<<NROWS, 256>>>(ref, p1_b);
    // MLP layer 1: split-K=2 (k slabs of 1568), then combine
    tc_gemm<0><<<dim3(4, 38, 2), t>>>(X, w1, nullptr, P, NROWS, 256, XCOLS, 1568);
    relu_combine_kernel<<<cdiv(NROWS * 256, 256), t>>>(P, b1, H1);
    // MLP layers 2..4
    tc_gemm<1><<<dim3(8, 38, 1), t>>>(H1, w2, b2, H2, NROWS, 512, 256, 256);
    tc_gemm<1><<<dim3(8, 38, 1), t>>>(H2, w3, b3, H3, NROWS, 512, 512, 512);
    tc_gemm<3><<<dim3(1, 38, 1), t>>>(H3, w4, b4, pts, NROWS, 16, 512, 512);
    // grid-sample recompute + gate + softmax combine
    finalize_kernel<<<BQ, 256>>>(memory, ref, a2w, a2b, out);
}

// round 4
// speedup vs baseline: 1.8210x; 1.4744x over previous
#include <cuda_runtime.h>
#include <cuda_bf16.h>
#include <math.h>
#include <stdint.h>

#define HIDDEN   256
#define NQ       300
#define BS       2
#define LVLS     4
#define NHEADS   8
#define TOTALPIX 21760
#define BQ       (BS*NQ)          // 600
#define NROWS    (LVLS*BS*NQ)     // 2400
#define XCOLS    3136

// ---------------- scratch (static device globals; no runtime alloc) ----------
__device__ float g_gate[BQ * NHEADS * HIDDEN];   // 600 x 2048
__device__ float g_proj[BS * TOTALPIX * 64];     // projected memory
__device__ float g_X  [NROWS * XCOLS];           // MLP input rows
__device__ float g_P  [2 * NROWS * 256];         // split-K partials
__device__ float g_H1 [NROWS * 256];
__device__ float g_H2 [NROWS * 512];
__device__ float g_H3 [NROWS * 512];
__device__ float g_pts[NROWS * 16];

__device__ __constant__ int c_dim[4]   = {128, 64, 32, 16};
__device__ __constant__ int c_start[4] = {0, 16384, 20480, 21504};

// ---------------- shared geometry helper (roi_align sampling) ----------------
__device__ __forceinline__ void sample4(float sx, float sy, float bw, float bh,
                                        int W, int si, int sj,
                                        int idx[4], float wt[4]) {
    float Wf = (float)W;
    float ty = (float)(si >> 1) + 0.25f + 0.5f * (float)(si & 1);
    float tx = (float)(sj >> 1) + 0.25f + 0.5f * (float)(sj & 1);
    float y = sy + bh * ty;
    float x = sx + bw * tx;
    bool valid = (y >= -1.f) && (y <= Wf) && (x >= -1.f) && (x <= Wf);
    float yc = fminf(fmaxf(y, 0.f), Wf - 1.f);
    float xc = fminf(fmaxf(x, 0.f), Wf - 1.f);
    float y0 = fminf(floorf(yc), Wf - 2.f);
    float x0 = fminf(floorf(xc), Wf - 2.f);
    float ly = yc - y0, lx = xc - x0;
    int yi = (int)y0, xi = (int)x0;
    int p = yi * W + xi;
    float vm = valid ? 0.25f : 0.f;
    float oy = 1.f - ly, ox = 1.f - lx;
    idx[0] = p;         wt[0] = oy * ox * vm;
    idx[1] = p + 1;     wt[1] = oy * lx * vm;
    idx[2] = p + W;     wt[2] = ly * ox * vm;
    idx[3] = p + W + 1; wt[3] = ly * lx * vm;
}

__device__ __forceinline__ void box_geom(const float* __restrict__ r6, int W,
                                         float& sx, float& sy, float& bw, float& bh) {
    float Wf = (float)W;
    float cx = r6[0], cy = r6[1];
    float x1 = fminf(fmaxf(cx - r6[2], 0.f), 1.f) * Wf;
    float y1 = fminf(fmaxf(cy - r6[3], 0.f), 1.f) * Wf;
    float x2 = fminf(fmaxf(cx + r6[4], 0.f), 1.f) * Wf;
    float y2 = fminf(fmaxf(cy + r6[5], 0.f), 1.f) * Wf;
    sx = x1 - 0.5f; sy = y1 - 0.5f;
    bw = (x2 - x1) / 7.f; bh = (y2 - y1) / 7.f;
}

// ================== 3xBF16 tensor-core GEMM (ldmatrix + m16n8k16) ============
// C = epi(A(MxK) @ B(KxN) + bias).  BM=BN=64, BK=32, 128 threads (4 warps).
// Warp grid 2(m) x 2(n); warp tile 32x32. hi/lo bf16 split computed at STS
// time into 4 SMEM planes (Ahi, Alo, Bhi, Blo), each XOR-swizzled for
// conflict-free ldmatrix + STS.128. gridDim.z = split-K slabs (writes
// C + z*M*N). K and kSplit must be multiples of 32; N multiple of 8.

__device__ __forceinline__ void cvt8(float4 u, float4 v, uint4& hi, uint4& lo) {
    __nv_bfloat162 h0 = __floats2bfloat162_rn(u.x, u.y);
    __nv_bfloat162 h1 = __floats2bfloat162_rn(u.z, u.w);
    __nv_bfloat162 h2 = __floats2bfloat162_rn(v.x, v.y);
    __nv_bfloat162 h3 = __floats2bfloat162_rn(v.z, v.w);
    hi.x = *(uint32_t*)&h0; hi.y = *(uint32_t*)&h1;
    hi.z = *(uint32_t*)&h2; hi.w = *(uint32_t*)&h3;
    __nv_bfloat162 l0 = __floats2bfloat162_rn(u.x - __bfloat162float(h0.x),
                                              u.y - __bfloat162float(h0.y));
    __nv_bfloat162 l1 = __floats2bfloat162_rn(u.z - __bfloat162float(h1.x),
                                              u.w - __bfloat162float(h1.y));
    __nv_bfloat162 l2 = __floats2bfloat162_rn(v.x - __bfloat162float(h2.x),
                                              v.y - __bfloat162float(h2.y));
    __nv_bfloat162 l3 = __floats2bfloat162_rn(v.z - __bfloat162float(h3.x),
                                              v.w - __bfloat162float(h3.y));
    lo.x = *(uint32_t*)&l0; lo.y = *(uint32_t*)&l1;
    lo.z = *(uint32_t*)&l2; lo.w = *(uint32_t*)&l3;
}

__device__ __forceinline__ void ldsm4(uint32_t r[4], uint32_t addr) {
    asm volatile("ldmatrix.sync.aligned.m8n8.x4.shared.b16 {%0,%1,%2,%3}, [%4];"
                 : "=r"(r[0]), "=r"(r[1]), "=r"(r[2]), "=r"(r[3]) : "r"(addr));
}
__device__ __forceinline__ void ldsm4t(uint32_t r[4], uint32_t addr) {
    asm volatile("ldmatrix.sync.aligned.m8n8.x4.trans.shared.b16 {%0,%1,%2,%3}, [%4];"
                 : "=r"(r[0]), "=r"(r[1]), "=r"(r[2]), "=r"(r[3]) : "r"(addr));
}
__device__ __forceinline__ void mma_bf16(float c[4], const uint32_t a[4], const uint32_t* b) {
    asm volatile(
        "mma.sync.aligned.m16n8k16.row.col.f32.bf16.bf16.f32 "
        "{%0,%1,%2,%3},{%4,%5,%6,%7},{%8,%9},{%0,%1,%2,%3};"
        : "+f"(c[0]), "+f"(c[1]), "+f"(c[2]), "+f"(c[3])
        : "r"(a[0]), "r"(a[1]), "r"(a[2]), "r"(a[3]), "r"(b[0]), "r"(b[1]));
}

template <int EPI>   // 0 none, 1 relu, 2 sigmoid, 3 tanh
__global__ __launch_bounds__(128, 4)
void bf_gemm(const float* __restrict__ A, const float* __restrict__ B,
             const float* __restrict__ bias, float* __restrict__ C,
             int M, int N, int K, int kSplit) {
    // planes: Ahi 0, Alo 4096, Bhi 8192, Blo 12288  (16 KB total)
    __shared__ __align__(16) unsigned char sm[16384];
    uint32_t sbase = (uint32_t)__cvta_generic_to_shared(sm);

    int bn0 = blockIdx.x * 64, bm0 = blockIdx.y * 64;
    int kS = blockIdx.z * kSplit;
    C += (size_t)blockIdx.z * M * N;

    int tid = threadIdx.x, warp = tid >> 5, lane = tid & 31;
    int wm0 = (warp & 1) * 32, wn0 = (warp >> 1) * 32;
    int lq = lane >> 2, lr = lane & 3;

    // loader task decode (two tasks per thread: e = tid, tid+128)
    int aM[2], aG[2], bK[2], bNg[2];
#pragma unroll
    for (int u = 0; u < 2; u++) {
        int e = tid + 128 * u;
        aM[u] = e >> 2; aG[u] = e & 3;       // A: 64 rows x 4 chunks(8 floats)
        bK[u] = e >> 3; bNg[u] = e & 7;      // B: 32 krows x 8 chunks(8 floats)
    }

    // ldmatrix per-lane address precompute
    int matSel = lane >> 3;                          // 0..3
    int rowA = (lane & 7) + ((matSel & 1) << 3);     // 0..15 within frag
    int cbitA = matSel >> 1;                         // k-chunk within k16
    int rA0 = wm0 + rowA, rA1 = wm0 + 16 + rowA;
    int swzA0 = (rA0 >> 1) & 3, swzA1 = (rA1 >> 1) & 3;
    uint32_t aRow0 = sbase + rA0 * 64;
    uint32_t aRow1 = sbase + rA1 * 64;

    int kr0 = (lane & 7) + ((matSel & 1) << 3);      // 0..15 (k within k16)
    int cb0 = (wn0 >> 3) + (matSel >> 1);            // n-chunk for nf pair 0/1
    int cb2 = cb0 + 2;                               // n-chunk for nf pair 2/3
    uint32_t bOff0 = sbase + 8192 + kr0 * 128 + ((uint32_t)(cb0 ^ (kr0 & 7)) << 4);
    uint32_t bOff2 = sbase + 8192 + kr0 * 128 + ((uint32_t)(cb2 ^ (kr0 & 7)) << 4);

    float acc[2][4][4];
#pragma unroll
    for (int i = 0; i < 2; i++)
#pragma unroll
        for (int j = 0; j < 4; j++)
#pragma unroll
            for (int k = 0; k < 4; k++) acc[i][j][k] = 0.f;

    float4 pa[2][2], pb[2][2];
    const float4 z4 = make_float4(0.f, 0.f, 0.f, 0.f);

    auto loadTile = [&](int t) {
#pragma unroll
        for (int u = 0; u < 2; u++) {
            int gm = bm0 + aM[u];
            int ka = kS + t * 32 + aG[u] * 8;
            if (gm < M) {
                const float* p = A + (size_t)gm * K + ka;
                pa[u][0] = *(const float4*)p; pa[u][1] = *(const float4*)(p + 4);
            } else { pa[u][0] = z4; pa[u][1] = z4; }
            int gn = bn0 + bNg[u] * 8;
            int kb = kS + t * 32 + bK[u];
            if (gn < N) {
                const float* p = B + (size_t)kb * N + gn;
                pb[u][0] = *(const float4*)p; pb[u][1] = *(const float4*)(p + 4);
            } else { pb[u][0] = z4; pb[u][1] = z4; }
        }
    };

    loadTile(0);
    int T = kSplit / 32;
    for (int t = 0; t < T; t++) {
        // convert + store tile to SMEM planes
#pragma unroll
        for (int u = 0; u < 2; u++) {
            uint4 hi, lo;
            cvt8(pa[u][0], pa[u][1], hi, lo);
            uint32_t off = aM[u] * 64 + ((uint32_t)(aG[u] ^ ((aM[u] >> 1) & 3)) << 4);
            *(uint4*)(sm + off) = hi;
            *(uint4*)(sm + 4096 + off) = lo;
            cvt8(pb[u][0], pb[u][1], hi, lo);
            off = 8192 + bK[u] * 128 + ((uint32_t)(bNg[u] ^ (bK[u] & 7)) << 4);
            *(uint4*)(sm + off) = hi;
            *(uint4*)(sm + 4096 + off) = lo;
        }
        __syncthreads();

        if (t + 1 < T) loadTile(t + 1);

#pragma unroll
        for (int s = 0; s < 2; s++) {
            uint32_t aH0[4], aL0[4], aH1[4], aL1[4];
            uint32_t ad0 = aRow0 + ((uint32_t)((2 * s + cbitA) ^ swzA0) << 4);
            uint32_t ad1 = aRow1 + ((uint32_t)((2 * s + cbitA) ^ swzA1) << 4);
            ldsm4(aH0, ad0); ldsm4(aL0, ad0 + 4096);
            ldsm4(aH1, ad1); ldsm4(aL1, ad1 + 4096);
            uint32_t bH01[4], bL01[4], bH23[4], bL23[4];
            uint32_t bd0 = bOff0 + s * 2048, bd2 = bOff2 + s * 2048;
            ldsm4t(bH01, bd0); ldsm4t(bL01, bd0 + 4096);
            ldsm4t(bH23, bd2); ldsm4t(bL23, bd2 + 4096);

#pragma unroll
            for (int mf = 0; mf < 2; mf++) {
                const uint32_t* aH = mf ? aH1 : aH0;
                const uint32_t* aL = mf ? aL1 : aL0;
#pragma unroll
                for (int nf = 0; nf < 4; nf++) {
                    const uint32_t* bH = (nf < 2) ? &bH01[(nf & 1) * 2] : &bH23[(nf & 1) * 2];
                    const uint32_t* bL = (nf < 2) ? &bL01[(nf & 1) * 2] : &bL23[(nf & 1) * 2];
                    mma_bf16(acc[mf][nf], aL, bH);
                    mma_bf16(acc[mf][nf], aH, bL);
                    mma_bf16(acc[mf][nf], aH, bH);
                }
            }
        }
        __syncthreads();
    }

    // epilogue
#pragma unroll
    for (int mf = 0; mf < 2; mf++)
#pragma unroll
        for (int nf = 0; nf < 4; nf++)
#pragma unroll
            for (int ci = 0; ci < 4; ci++) {
                int m = bm0 + wm0 + mf * 16 + lq + ((ci >= 2) ? 8 : 0);
                int n = bn0 + wn0 + nf * 8 + lr * 2 + (ci & 1);
                if (m >= M || n >= N) continue;
                float v = acc[mf][nf][ci] + (bias ? bias[n] : 0.f);
                if (EPI == 1) v = fmaxf(v, 0.f);
                else if (EPI == 2) v = 1.f / (1.f + expf(-v));
                else if (EPI == 3) v = tanhf(v);
                C[(size_t)m * N + n] = v;
            }
}

// ---------------- split-K combine: H1 = relu(P0 + P1 + b1) -------------------
__global__ __launch_bounds__(256)
void relu_combine_kernel(const float* __restrict__ P, const float* __restrict__ bias,
                         float* __restrict__ H) {
    int i = blockIdx.x * 256 + threadIdx.x;
    if (i < NROWS * 256) {
        float v = P[i] + P[i + NROWS * 256] + bias[i & 255];
        H[i] = fmaxf(v, 0.f);
    }
}

// ---------------- build X rows: relu(roi_align(proj) + p1_b), flattened ------
__global__ __launch_bounds__(256)
void build_x_kernel(const float* __restrict__ ref, const float* __restrict__ p1_b) {
    int blk = blockIdx.x;                 // lvl*600 + b*300 + q
    int lvl = blk / BQ;
    int rem = blk - lvl * BQ;
    int b = rem / NQ;
    int q = rem - b * NQ;
    int W = c_dim[lvl];
    int start = c_start[lvl];
    const float* r6 = ref + ((size_t)(b * NQ + q) * LVLS + lvl) * 6;
    float sx, sy, bw, bh;
    box_geom(r6, W, sx, sy, bw, bh);

    __shared__ int   sIdx[196][4];
    __shared__ float sW[196][4];
    int tid = threadIdx.x;
    if (tid < 196) {
        int si = tid / 14, sj = tid - si * 14;
        int idx4[4]; float wt4[4];
        sample4(sx, sy, bw, bh, W, si, sj, idx4, wt4);
#pragma unroll
        for (int k = 0; k < 4; k++) { sIdx[tid][k] = idx4[k]; sW[tid][k] = wt4[k]; }
    }
    __syncthreads();

    int d = tid & 63;
    int g = tid >> 6;                      // 0..3
    const float* projB = g_proj + ((size_t)b * TOTALPIX + start) * 64 + d;
    float bias = p1_b[d];
    float* Xrow = g_X + (size_t)blk * XCOLS + d * 49;
    for (int bin = g; bin < 49; bin += 4) {
        int h = bin / 7, w_ = bin - h * 7;
        float acc = 0.f;
#pragma unroll
        for (int s2 = 0; s2 < 4; s2++) {
            int s = (2 * h + (s2 >> 1)) * 14 + 2 * w_ + (s2 & 1);
#pragma unroll
            for (int cr = 0; cr < 4; cr++)
                acc += sW[s][cr] * projB[(size_t)sIdx[s][cr] * 64];
        }
        Xrow[bin] = fmaxf(acc + bias, 0.f);
    }
}

// ---------------- finalize: grid_sample recompute + gate + softmax combine ---
__global__ __launch_bounds__(256)
void finalize_kernel(const float* __restrict__ memory, const float* __restrict__ ref,
                     const float* __restrict__ a2w, const float* __restrict__ a2b,
                     float* __restrict__ out) {
    int bq = blockIdx.x;                   // b*300 + q
    int b = bq / NQ;
    int tid = threadIdx.x;

    __shared__ float qe_s[32][HIDDEN];     // 32 KB
    __shared__ float wArr[2048];           // 8 KB
    __shared__ unsigned short iArr[2048];  // 4 KB
    __shared__ float logits[32];
    __shared__ float wgt[32];

    for (int e = tid; e < 2048; e += 256) {
        int lvl = e >> 9;
        int head = (e >> 6) & 7;
        int bc = (e >> 4) & 3;
        int sm = (e >> 2) & 3;
        int cr = e & 3;
        int W = c_dim[lvl];
        int start = c_start[lvl];
        const float* r6 = ref + ((size_t)bq * LVLS + lvl) * 6;
        float sx, sy, bw, bh;
        box_geom(r6, W, sx, sy, bw, bh);

        int row = lvl * BQ + bq;
        float gx = g_pts[row * 16 + 2 * head];
        float gy = g_pts[row * 16 + 2 * head + 1];
        float ix = ((gx + 1.f) * 7.f - 1.f) * 0.5f;
        float iy = ((gy + 1.f) * 7.f - 1.f) * 0.5f;
        float bxf = floorf(ix), byf = floorf(iy);
        float lx = ix - bxf, ly = iy - byf;
        int dby = bc >> 1, dbx = bc & 1;
        int bi = (int)byf + dby, bj = (int)bxf + dbx;
        float wb = (dby ? ly : 1.f - ly) * (dbx ? lx : 1.f - lx);
        if (bi < 0 || bi > 6 || bj < 0 || bj > 6) wb = 0.f;
        int si = 2 * bi + (sm >> 1);
        int sj = 2 * bj + (sm & 1);
        int idx4[4]; float wt4[4];
        sample4(sx, sy, bw, bh, W, si, sj, idx4, wt4);
        wArr[e] = wb * wt4[cr];
        iArr[e] = (unsigned short)(b * TOTALPIX + start + idx4[cr]);
    }
    __syncthreads();

    const float* gateRow = g_gate + (size_t)bq * (NHEADS * HIDDEN);
    int c = tid;
    for (int lh = 0; lh < 32; lh++) {
        float a0 = 0.f, a1 = 0.f, a2 = 0.f, a3 = 0.f;
        int eb = lh << 6;
#pragma unroll 4
        for (int e = 0; e < 64; e += 4) {
            float w0 = wArr[eb + e + 0];
            float w1 = wArr[eb + e + 1];
            float w2 = wArr[eb + e + 2];
            float w3 = wArr[eb + e + 3];
            if (w0 != 0.f) a0 += w0 * memory[(size_t)iArr[eb + e + 0] * HIDDEN + c];
            if (w1 != 0.f) a1 += w1 * memory[(size_t)iArr[eb + e + 1] * HIDDEN + c];
            if (w2 != 0.f) a2 += w2 * memory[(size_t)iArr[eb + e + 2] * HIDDEN + c];
            if (w3 != 0.f) a3 += w3 * memory[(size_t)iArr[eb + e + 3] * HIDDEN + c];
        }
        qe_s[lh][c] = ((a0 + a1) + (a2 + a3)) * gateRow[(lh & 7) * HIDDEN + c];
    }
    __syncthreads();

    int warp = tid >> 5, lane = tid & 31;
    for (int r = warp; r < 32; r += 8) {
        float s = 0.f;
#pragma unroll
        for (int c2 = lane; c2 < HIDDEN; c2 += 32) s += qe_s[r][c2] * a2w[c2];
#pragma unroll
        for (int o = 16; o; o >>= 1) s += __shfl_xor_sync(0xffffffffu, s, o);
        if (lane == 0) logits[r] = s + a2b[0];
    }
    __syncthreads();

    if (tid < 32) {
        float l = logits[tid];
        float mx = l;
#pragma unroll
        for (int o = 16; o; o >>= 1) mx = fmaxf(mx, __shfl_xor_sync(0xffffffffu, mx, o));
        float ex = expf(l - mx);
        float sum = ex;
#pragma unroll
        for (int o = 16; o; o >>= 1) sum += __shfl_xor_sync(0xffffffffu, sum, o);
        wgt[tid] = ex / sum;
    }
    __syncthreads();

    float o = 0.f;
#pragma unroll
    for (int r = 0; r < 32; r++) o += wgt[r] * qe_s[r][c];
    out[(size_t)bq * HIDDEN + c] = o;
}

// -----------------------------------------------------------------------------
static inline int cdiv(int a, int b) { return (a + b - 1) / b; }

extern "C" void kernel_launch(void* const* d_in, const int* in_sizes, int n_in,
                              void* d_out, int out_size) {
    const float* tgt    = (const float*)d_in[0];
    const float* memory = (const float*)d_in[1];
    const float* ref    = (const float*)d_in[2];
    const float* p1_w = (const float*)d_in[4];
    const float* p1_b = (const float*)d_in[5];
    const float* w1   = (const float*)d_in[6];
    const float* b1   = (const float*)d_in[7];
    const float* w2   = (const float*)d_in[8];
    const float* b2   = (const float*)d_in[9];
    const float* w3   = (const float*)d_in[10];
    const float* b3   = (const float*)d_in[11];
    const float* w4   = (const float*)d_in[12];
    const float* b4   = (const float*)d_in[13];
    const float* a1w  = (const float*)d_in[14];
    const float* a1b  = (const float*)d_in[15];
    const float* a2w  = (const float*)d_in[16];
    const float* a2b  = (const float*)d_in[17];
    float* out = (float*)d_out;

    float *gate, *proj, *X, *P, *H1, *H2, *H3, *pts;
    cudaGetSymbolAddress((void**)&gate, g_gate);
    cudaGetSymbolAddress((void**)&proj, g_proj);
    cudaGetSymbolAddress((void**)&X,    g_X);
    cudaGetSymbolAddress((void**)&P,    g_P);
    cudaGetSymbolAddress((void**)&H1,   g_H1);
    cudaGetSymbolAddress((void**)&H2,   g_H2);
    cudaGetSymbolAddress((void**)&H3,   g_H3);
    cudaGetSymbolAddress((void**)&pts,  g_pts);

    dim3 t(128);
    // gate = sigmoid(tgt @ attn1_w + attn1_b)   (600 x 2048, K=256)
    bf_gemm<2><<<dim3(32, 10, 1), t>>>(tgt, a1w, a1b, gate, BQ, 2048, 256, 256);
    // proj = memory @ p1_w                       (43520 x 64, K=256)
    bf_gemm<0><<<dim3(1, 680, 1), t>>>(memory, p1_w, nullptr, proj, BS * TOTALPIX, 64, 256, 256);
    // X rows via roi_align on projected memory
    build_x_kernel<<<NROWS, 256>>>(ref, p1_b);
    // MLP layer 1: split-K=2 (k slabs of 1568), then combine
    bf_gemm<0><<<dim3(4, 38, 2), t>>>(X, w1, nullptr, P, NROWS, 256, XCOLS, 1568);
    relu_combine_kernel<<<cdiv(NROWS * 256, 256), 256>>>(P, b1, H1);
    // MLP layers 2..4
    bf_gemm<1><<<dim3(8, 38, 1), t>>>(H1, w2, b2, H2, NROWS, 512, 256, 256);
    bf_gemm<1><<<dim3(8, 38, 1), t>>>(H2, w3, b3, H3, NROWS, 512, 512, 512);
    bf_gemm<3><<<dim3(1, 38, 1), t>>>(H3, w4, b4, pts, NROWS, 16, 512, 512);
    // grid-sample recompute + gate + softmax combine
    finalize_kernel<<<BQ, 256>>>(memory, ref, a2w, a2b, out);
}